// round 8
// baseline (speedup 1.0000x reference)
#include <cuda_runtime.h>
#include <cuda_bf16.h>
#include <math.h>
#include <stdint.h>

#define BQ 8
#define TT 512
#define CC 512
#define HH 8
#define DHD 64
#define LL 2
#define MM (BQ * TT)
#define FF (4 * CC)
#define STEPS 4
typedef __nv_bfloat16 bf16;
typedef long long ll;

// ------------------------- scratch (__device__ globals) --------------------
__device__ __align__(16) float g_x[MM * CC];
__device__ __align__(16) float g_att[BQ * HH * TT * TT];
__device__ __align__(16) float g_bqkv[LL * 3 * CC];
__device__ __align__(16) bf16 g_xnh[MM * CC], g_xnl[MM * CC];
__device__ __align__(16) bf16 g_qkvh[MM * 3 * CC], g_qkvl[MM * 3 * CC];
__device__ __align__(16) bf16 g_yh[MM * CC],  g_yl[MM * CC];
__device__ __align__(16) bf16 g_hh[MM * FF],  g_hl[MM * FF];
__device__ __align__(16) bf16 g_ph[BQ * HH * TT * TT], g_pl[BQ * HH * TT * TT];
#define NW 6553600
__device__ __align__(16) bf16 g_wh[NW], g_wl[NW];
#define WOFF_L   3145728
#define WOFF_QKV 0
#define WOFF_Q   0
#define WOFF_K   262144
#define WOFF_V   524288
#define WOFF_P   786432
#define WOFF_1   1048576
#define WOFF_2   2097152
#define WOFF_HD  6291456

// ------------------------- helpers -----------------------------------------
__device__ __forceinline__ void split1(float v, bf16 &h, bf16 &l) {
    h = __float2bfloat16(v);
    l = __float2bfloat16(v - __bfloat162float(h));
}
__device__ __forceinline__ void split2(float x, float y, unsigned &hi, unsigned &lo) {
    bf16 hx, lx, hy, ly;
    split1(x, hx, lx); split1(y, hy, ly);
    hi = ((unsigned)__bfloat16_as_ushort(hy) << 16) | (unsigned)__bfloat16_as_ushort(hx);
    lo = ((unsigned)__bfloat16_as_ushort(ly) << 16) | (unsigned)__bfloat16_as_ushort(lx);
}
__device__ __forceinline__ unsigned smem_u32(const void *p) {
    return (unsigned)__cvta_generic_to_shared(p);
}
__device__ __forceinline__ float gelu_exact(float x) {
    return 0.5f * x * (1.0f + erff(x * 0.7071067811865476f));
}
__device__ __forceinline__ void mma_bf16(float *d, const unsigned *a, unsigned b0, unsigned b1) {
    asm volatile(
        "mma.sync.aligned.m16n8k16.row.col.f32.bf16.bf16.f32 "
        "{%0,%1,%2,%3}, {%4,%5,%6,%7}, {%8,%9}, {%0,%1,%2,%3};\n"
        : "+f"(d[0]), "+f"(d[1]), "+f"(d[2]), "+f"(d[3])
        : "r"(a[0]), "r"(a[1]), "r"(a[2]), "r"(a[3]), "r"(b0), "r"(b1));
}
#define LDSM4(R0, R1, R2, R3, ADDR) \
    asm volatile("ldmatrix.sync.aligned.m8n8.x4.shared.b16 {%0,%1,%2,%3}, [%4];" \
                 : "=r"(R0), "=r"(R1), "=r"(R2), "=r"(R3) : "r"(ADDR))
#define LDSM4T(R0, R1, R2, R3, ADDR) \
    asm volatile("ldmatrix.sync.aligned.m8n8.x4.trans.shared.b16 {%0,%1,%2,%3}, [%4];" \
                 : "=r"(R0), "=r"(R1), "=r"(R2), "=r"(R3) : "r"(ADDR))
#define CP16(dst, src) \
    asm volatile("cp.async.cg.shared.global [%0], [%1], 16;" :: "r"(dst), "l"(src))
#define CP_COMMIT() asm volatile("cp.async.commit_group;" ::: "memory")
#define CP_WAIT1()  asm volatile("cp.async.wait_group 1;" ::: "memory")
#define CP_WAIT0()  asm volatile("cp.async.wait_group 0;" ::: "memory")

// ------------------------- HMMA GEMM (bf16 split, 3-stage pipeline) --------
// D[M,N] = Ahi@Bhi + Ahi@Blo + Alo@Bhi (+bias). A K-major [m][k].
// transB=1: B [N,K] (C=A@B^T); transB=0: B [K,N].
// Tile 128x64xK32, 8 warps (warp 32x32), 3-stage cp.async, 1 barrier/chunk.
// ep: 0 Cf=acc+bias; 1 split(gelu); 2 Cf+=; 3 split store.
#define APITCH 40
#define BPT    40
#define BPN    72
// per-stage (bf16 elems): Ah 5120 | Al 5120 | Bh 2560 | Bl 2560 = 15360 (30720 B)
#define STAGE_B 30720u
#define SMEM_BYTES (3 * 30720)

__global__ __launch_bounds__(256, 2)
void gemm_hmma(const bf16 *__restrict__ Ah_, const bf16 *__restrict__ Al_, int lda,
               ll sA0, ll sA1,
               const bf16 *__restrict__ Bh_, const bf16 *__restrict__ Bl_, int ldb,
               ll sB0, ll sB1,
               float *__restrict__ Cf, bf16 *__restrict__ Coh, bf16 *__restrict__ Col,
               int ldc, ll sC0, ll sC1,
               int K, int zdiv, const float *__restrict__ bias, int transB, int ep)
{
    extern __shared__ __align__(16) bf16 sm[];
    int z = blockIdx.z;
    ll zo0 = z / zdiv, zo1 = z % zdiv;
    Ah_ += zo0 * sA0 + zo1 * sA1;  Al_ += zo0 * sA0 + zo1 * sA1;
    Bh_ += zo0 * sB0 + zo1 * sB1;  Bl_ += zo0 * sB0 + zo1 * sB1;
    ll coff = zo0 * sC0 + zo1 * sC1;
    int n0 = blockIdx.x * 64, m0 = blockIdx.y * 128;

    int t = threadIdx.x, lane = t & 31, warp = t >> 5;
    int wm = (warp & 3) << 5, wn = (warp >> 2) << 5;
    int gg = lane >> 2, cc2 = (lane & 3) << 1;

    int a_ck = (t & 3) << 3, a_rw = t >> 2;
    int bt_rw = t >> 2, bt_ck = (t & 3) << 3;
    int bn_rw = t >> 3, bn_ck = (t & 7) << 3;

    unsigned sb = smem_u32(sm);

    int sel = lane >> 3, lr = lane & 7;
    int ar_g = lr + ((sel & 1) ? 8 : 0);
    int a_cs = (sel & 2) ? 8 : 0;
    int btr_g = lr + ((sel & 2) ? 8 : 0);
    int bt_cs = (sel & 1) ? 8 : 0;
    int bnr_g = lr + ((sel & 1) ? 8 : 0);
    int bn_cs = (sel & 2) ? 8 : 0;

    float acc[2][4][4];
#pragma unroll
    for (int mi = 0; mi < 2; mi++)
#pragma unroll
        for (int j = 0; j < 4; j++)
#pragma unroll
            for (int r = 0; r < 4; r++) acc[mi][j][r] = 0.f;

#define ISSUE(S, K0) do { \
    unsigned bb = sb + (unsigned)(S) * STAGE_B; \
    _Pragma("unroll") \
    for (int p = 0; p < 2; p++) { \
        int row = a_rw + 64 * p; \
        ll go = (ll)(m0 + row) * lda + (K0) + a_ck; \
        unsigned d = (unsigned)((row * APITCH + a_ck) * 2); \
        CP16(bb + d, Ah_ + go); \
        CP16(bb + 10240u + d, Al_ + go); \
    } \
    if (transB) { \
        ll go = (ll)(n0 + bt_rw) * ldb + (K0) + bt_ck; \
        unsigned d = (unsigned)((bt_rw * BPT + bt_ck) * 2); \
        CP16(bb + 20480u + d, Bh_ + go); \
        CP16(bb + 25600u + d, Bl_ + go); \
    } else { \
        ll go = (ll)((K0) + bn_rw) * ldb + n0 + bn_ck; \
        unsigned d = (unsigned)((bn_rw * BPN + bn_ck) * 2); \
        CP16(bb + 20480u + d, Bh_ + go); \
        CP16(bb + 25600u + d, Bl_ + go); \
    } \
    CP_COMMIT(); \
} while (0)

    int nk = K >> 5;
    ISSUE(0, 0);
    if (nk > 1) ISSUE(1, 32);

    for (int c = 0; c < nk; c++) {
        if (c + 1 < nk) CP_WAIT1(); else CP_WAIT0();
        __syncthreads();
        if (c + 2 < nk) ISSUE((c + 2) % 3, (c + 2) << 5);

        unsigned bb = sb + (unsigned)(c % 3) * STAGE_B;
        unsigned aoh = bb, aol = bb + 10240u, boh = bb + 20480u, bol = bb + 25600u;
#pragma unroll
        for (int ks = 0; ks < 2; ks++) {
            int kb = ks << 4;
            unsigned ah[2][4], al2[2][4];
#pragma unroll
            for (int mi = 0; mi < 2; mi++) {
                unsigned off = (unsigned)(((wm + 16 * mi + ar_g) * APITCH + kb + a_cs) * 2);
                LDSM4(ah[mi][0], ah[mi][1], ah[mi][2], ah[mi][3], aoh + off);
                LDSM4(al2[mi][0], al2[mi][1], al2[mi][2], al2[mi][3], aol + off);
            }
            unsigned bh[4][2], bl2[4][2];
#pragma unroll
            for (int p = 0; p < 2; p++) {
                if (transB) {
                    unsigned off = (unsigned)(((wn + 16 * p + btr_g) * BPT + kb + bt_cs) * 2);
                    LDSM4(bh[2 * p][0], bh[2 * p][1], bh[2 * p + 1][0], bh[2 * p + 1][1], boh + off);
                    LDSM4(bl2[2 * p][0], bl2[2 * p][1], bl2[2 * p + 1][0], bl2[2 * p + 1][1], bol + off);
                } else {
                    unsigned off = (unsigned)(((kb + bnr_g) * BPN + wn + 16 * p + bn_cs) * 2);
                    LDSM4T(bh[2 * p][0], bh[2 * p][1], bh[2 * p + 1][0], bh[2 * p + 1][1], boh + off);
                    LDSM4T(bl2[2 * p][0], bl2[2 * p][1], bl2[2 * p + 1][0], bl2[2 * p + 1][1], bol + off);
                }
            }
#pragma unroll
            for (int mi = 0; mi < 2; mi++)
#pragma unroll
                for (int j = 0; j < 4; j++) {
                    mma_bf16(acc[mi][j], ah[mi], bh[j][0], bh[j][1]);
                    mma_bf16(acc[mi][j], ah[mi], bl2[j][0], bl2[j][1]);
                    mma_bf16(acc[mi][j], al2[mi], bh[j][0], bh[j][1]);
                }
        }
    }

#pragma unroll
    for (int mi = 0; mi < 2; mi++)
#pragma unroll
        for (int j = 0; j < 4; j++) {
            int col = n0 + wn + (j << 3) + cc2;
            int row = m0 + wm + (mi << 4) + gg;
            float b0v = bias ? bias[col] : 0.f;
            float b1v = bias ? bias[col + 1] : 0.f;
            float v00 = acc[mi][j][0] + b0v, v01 = acc[mi][j][1] + b1v;
            float v10 = acc[mi][j][2] + b0v, v11 = acc[mi][j][3] + b1v;
            ll g0 = (ll)row * ldc + col + coff;
            ll g1 = (ll)(row + 8) * ldc + col + coff;
            if (ep == 0) {
                *(float2 *)(Cf + g0) = make_float2(v00, v01);
                *(float2 *)(Cf + g1) = make_float2(v10, v11);
            } else if (ep == 2) {
                float2 o0 = *(float2 *)(Cf + g0), o1 = *(float2 *)(Cf + g1);
                *(float2 *)(Cf + g0) = make_float2(o0.x + v00, o0.y + v01);
                *(float2 *)(Cf + g1) = make_float2(o1.x + v10, o1.y + v11);
            } else {
                if (ep == 1) {
                    v00 = gelu_exact(v00); v01 = gelu_exact(v01);
                    v10 = gelu_exact(v10); v11 = gelu_exact(v11);
                }
                unsigned hi, lo;
                split2(v00, v01, hi, lo);
                *(unsigned *)(Coh + g0) = hi; *(unsigned *)(Col + g0) = lo;
                split2(v10, v11, hi, lo);
                *(unsigned *)(Coh + g1) = hi; *(unsigned *)(Col + g1) = lo;
            }
        }
}

// ------------------------- one-time weight transpose+split -----------------
__global__ __launch_bounds__(256)
void wconv_kernel(const float *__restrict__ W, bf16 *__restrict__ th,
                  bf16 *__restrict__ tl, int K, int N)
{
    __shared__ float tile[32][33];
    int bx = blockIdx.x * 32, by = blockIdx.y * 32;
    int tx = threadIdx.x & 31, ty = threadIdx.x >> 5;
#pragma unroll
    for (int j = 0; j < 4; j++) {
        int kk = ty + j * 8;
        tile[kk][tx] = W[(ll)(by + kk) * N + bx + tx];
    }
    __syncthreads();
#pragma unroll
    for (int j = 0; j < 4; j++) {
        int nn = ty + j * 8;
        float v = tile[tx][nn];
        bf16 h, l;
        split1(v, h, l);
        ll o = (ll)(bx + nn) * K + by + tx;
        th[o] = h; tl[o] = l;
    }
}

__global__ void bcat_kernel(const float *__restrict__ bq, const float *__restrict__ bk,
                            const float *__restrict__ bv, float *__restrict__ dst)
{
    int i = blockIdx.x * 256 + threadIdx.x;
    if (i >= LL * 3 * CC) return;
    int l = i / (3 * CC), c = i % (3 * CC);
    float v;
    if (c < CC) v = bq[l * CC + c];
    else if (c < 2 * CC) v = bk[l * CC + c - CC];
    else v = bv[l * CC + c - 2 * CC];
    dst[i] = v;
}

// ------------------------- element kernels ---------------------------------
__global__ void embed_kernel(const int *__restrict__ idx, const float *__restrict__ tok,
                             const float *__restrict__ pos, float *__restrict__ x)
{
    int i = blockIdx.x * 256 + threadIdx.x;
    if (i >= MM * CC) return;
    int c = i & (CC - 1);
    int bt = i >> 9;
    int tp = bt & (TT - 1);
    x[i] = tok[idx[bt] * CC + c] + pos[tp * CC + c];
}

__global__ __launch_bounds__(256)
void ln_kernel(const float *__restrict__ x, bf16 *__restrict__ oh, bf16 *__restrict__ ol,
               const float *__restrict__ gam, const float *__restrict__ bet)
{
    __shared__ float red[256];
    int row = blockIdx.x, t = threadIdx.x;
    const float *xr = x + (ll)row * CC;
    float a = xr[t], b = xr[t + 256];
    red[t] = a + b;
    __syncthreads();
    for (int off = 128; off > 0; off >>= 1) {
        if (t < off) red[t] += red[t + off];
        __syncthreads();
    }
    float mu = red[0] * (1.0f / CC);
    __syncthreads();
    float da = a - mu, db = b - mu;
    red[t] = da * da + db * db;
    __syncthreads();
    for (int off = 128; off > 0; off >>= 1) {
        if (t < off) red[t] += red[t + off];
        __syncthreads();
    }
    float rstd = rsqrtf(red[0] * (1.0f / CC) + 1e-5f);
    float r0 = da * rstd * gam[t] + bet[t];
    float r1 = db * rstd * gam[t + 256] + bet[t + 256];
    bf16 h, l;
    ll o = (ll)row * CC;
    split1(r0, h, l); oh[o + t] = h;       ol[o + t] = l;
    split1(r1, h, l); oh[o + t + 256] = h; ol[o + t + 256] = l;
}

__global__ __launch_bounds__(128)
void softmax_kernel(const float *__restrict__ att, bf16 *__restrict__ ph,
                    bf16 *__restrict__ pl)
{
    __shared__ float red[128];
    int row = blockIdx.x, t = threadIdx.x;
    const float *p = att + (ll)row * TT;
    float v[4];
    float m = -1e30f;
#pragma unroll
    for (int i = 0; i < 4; i++) { v[i] = p[t + (i << 7)] * 0.125f; m = fmaxf(m, v[i]); }
    red[t] = m; __syncthreads();
    for (int off = 64; off > 0; off >>= 1) {
        if (t < off) red[t] = fmaxf(red[t], red[t + off]);
        __syncthreads();
    }
    m = red[0]; __syncthreads();
    float s = 0.f;
#pragma unroll
    for (int i = 0; i < 4; i++) { v[i] = __expf(v[i] - m); s += v[i]; }
    red[t] = s; __syncthreads();
    for (int off = 64; off > 0; off >>= 1) {
        if (t < off) red[t] += red[t + off];
        __syncthreads();
    }
    float inv = 1.0f / red[0];
    ll o = (ll)row * TT;
#pragma unroll
    for (int i = 0; i < 4; i++) {
        bf16 h, l;
        split1(v[i] * inv, h, l);
        ph[o + t + (i << 7)] = h;
        pl[o + t + (i << 7)] = l;
    }
}

// ------------------------- host orchestration ------------------------------
static void run_hm(const bf16 *Ah, const bf16 *Al, int lda, ll sA0, ll sA1,
                   const bf16 *Bh, const bf16 *Bl, int ldb, ll sB0, ll sB1,
                   float *Cf, bf16 *Coh, bf16 *Col, int ldc, ll sC0, ll sC1,
                   int Mr, int Nc, int K, int zdiv, int Z,
                   const float *bias, int transB, int ep)
{
    dim3 g(Nc / 64, Mr / 128, Z);
    gemm_hmma<<<g, 256, SMEM_BYTES>>>(Ah, Al, lda, sA0, sA1, Bh, Bl, ldb, sB0, sB1,
                                      Cf, Coh, Col, ldc, sC0, sC1, K, zdiv, bias, transB, ep);
}

extern "C" void kernel_launch(void *const *d_in, const int *in_sizes, int n_in,
                              void *d_out, int out_size)
{
    (void)in_sizes; (void)n_in; (void)out_size;
    const int   *idx  = (const int *)d_in[0];
    const float *tok  = (const float *)d_in[1];
    const float *pos  = (const float *)d_in[2];
    const float *ln1g = (const float *)d_in[3];
    const float *ln1b = (const float *)d_in[4];
    const float *Wq   = (const float *)d_in[5];
    const float *bq   = (const float *)d_in[6];
    const float *Wk   = (const float *)d_in[7];
    const float *bk   = (const float *)d_in[8];
    const float *Wv   = (const float *)d_in[9];
    const float *bv   = (const float *)d_in[10];
    const float *Wp   = (const float *)d_in[11];
    const float *bp   = (const float *)d_in[12];
    const float *ln2g = (const float *)d_in[13];
    const float *ln2b = (const float *)d_in[14];
    const float *W1   = (const float *)d_in[15];
    const float *b1   = (const float *)d_in[16];
    const float *W2   = (const float *)d_in[17];
    const float *b2   = (const float *)d_in[18];
    const float *lnfg = (const float *)d_in[19];
    const float *lnfb = (const float *)d_in[20];
    const float *Wh   = (const float *)d_in[21];
    float *out = (float *)d_out;

    static int smem_set = 0;
    if (!smem_set) {
        cudaFuncSetAttribute(gemm_hmma, cudaFuncAttributeMaxDynamicSharedMemorySize, SMEM_BYTES);
        smem_set = 1;
    }

    float *x, *att, *bqkv;
    bf16 *xnh, *xnl, *qkvh, *qkvl, *yh, *yl, *hh, *hl, *ph, *pl, *wh, *wl;
    cudaGetSymbolAddress((void **)&x, g_x);
    cudaGetSymbolAddress((void **)&att, g_att);
    cudaGetSymbolAddress((void **)&bqkv, g_bqkv);
    cudaGetSymbolAddress((void **)&xnh, g_xnh);   cudaGetSymbolAddress((void **)&xnl, g_xnl);
    cudaGetSymbolAddress((void **)&qkvh, g_qkvh); cudaGetSymbolAddress((void **)&qkvl, g_qkvl);
    cudaGetSymbolAddress((void **)&yh, g_yh);     cudaGetSymbolAddress((void **)&yl, g_yl);
    cudaGetSymbolAddress((void **)&hh, g_hh);     cudaGetSymbolAddress((void **)&hl, g_hl);
    cudaGetSymbolAddress((void **)&ph, g_ph);     cudaGetSymbolAddress((void **)&pl, g_pl);
    cudaGetSymbolAddress((void **)&wh, g_wh);     cudaGetSymbolAddress((void **)&wl, g_wl);

    dim3 tb(256);
    for (int l = 0; l < LL; l++) {
        ll wb = (ll)l * WOFF_L;
        wconv_kernel<<<dim3(CC / 32, CC / 32), tb>>>(Wq + l * CC * CC, wh + wb + WOFF_Q, wl + wb + WOFF_Q, CC, CC);
        wconv_kernel<<<dim3(CC / 32, CC / 32), tb>>>(Wk + l * CC * CC, wh + wb + WOFF_K, wl + wb + WOFF_K, CC, CC);
        wconv_kernel<<<dim3(CC / 32, CC / 32), tb>>>(Wv + l * CC * CC, wh + wb + WOFF_V, wl + wb + WOFF_V, CC, CC);
        wconv_kernel<<<dim3(CC / 32, CC / 32), tb>>>(Wp + l * CC * CC, wh + wb + WOFF_P, wl + wb + WOFF_P, CC, CC);
        wconv_kernel<<<dim3(FF / 32, CC / 32), tb>>>(W1 + (ll)l * CC * FF, wh + wb + WOFF_1, wl + wb + WOFF_1, CC, FF);
        wconv_kernel<<<dim3(CC / 32, FF / 32), tb>>>(W2 + (ll)l * FF * CC, wh + wb + WOFF_2, wl + wb + WOFF_2, FF, CC);
    }
    wconv_kernel<<<dim3(CC / 32, CC / 32), tb>>>(Wh, wh + WOFF_HD, wl + WOFF_HD, CC, CC);
    bcat_kernel<<<(LL * 3 * CC + 255) / 256, 256>>>(bq, bk, bv, bqkv);

    embed_kernel<<<(MM * CC + 255) / 256, 256>>>(idx, tok, pos, x);

    const ll TC = (ll)TT * CC;
    const ll T2 = (ll)TT * TT;
    const ll QKVROW = 3 * CC;                 // 1536
    const ll SBATCH = (ll)TT * QKVROW;        // per-batch stride in qkv

    for (int s = 0; s < STEPS; s++) {
        for (int l = 0; l < LL; l++) {
            ll wb = (ll)l * WOFF_L;
            ln_kernel<<<MM, 256>>>(x, xnh, xnl, ln1g + l * CC, ln1b + l * CC);
            // fused QKV: [4096,512] @ [1536,512]^T -> [4096,1536]
            run_hm(xnh, xnl, CC, 0, 0, wh + wb + WOFF_QKV, wl + wb + WOFF_QKV, CC, 0, 0,
                   nullptr, qkvh, qkvl, (int)QKVROW, 0, 0,
                   MM, (int)QKVROW, CC, 1, 1, bqkv + l * QKVROW, 1, 3);
            // scores[b,h] = Q @ K^T   (z = b*8 + h)
            run_hm(qkvh, qkvl, (int)QKVROW, SBATCH, DHD,
                   qkvh + CC, qkvl + CC, (int)QKVROW, SBATCH, DHD,
                   att, nullptr, nullptr, TT, (ll)HH * T2, T2,
                   TT, TT, DHD, HH, BQ * HH, nullptr, 1, 0);
            softmax_kernel<<<BQ * HH * TT, 128>>>(att, ph, pl);
            // y = P @ V  (V rows = kt, cols = d -> transB=0)
            run_hm(ph, pl, TT, (ll)HH * T2, T2,
                   qkvh + 2 * CC, qkvl + 2 * CC, (int)QKVROW, SBATCH, DHD,
                   nullptr, yh, yl, CC, TC, DHD,
                   TT, DHD, TT, HH, BQ * HH, nullptr, 0, 3);
            // x += y @ Wp + bp
            run_hm(yh, yl, CC, 0, 0, wh + wb + WOFF_P, wl + wb + WOFF_P, CC, 0, 0,
                   x, nullptr, nullptr, CC, 0, 0, MM, CC, CC, 1, 1, bp + l * CC, 1, 2);
            ln_kernel<<<MM, 256>>>(x, xnh, xnl, ln2g + l * CC, ln2b + l * CC);
            // h = gelu(xn @ W1 + b1)
            run_hm(xnh, xnl, CC, 0, 0, wh + wb + WOFF_1, wl + wb + WOFF_1, CC, 0, 0,
                   nullptr, hh, hl, FF, 0, 0, MM, FF, CC, 1, 1, b1 + l * FF, 1, 1);
            // x += h @ W2 + b2
            run_hm(hh, hl, FF, 0, 0, wh + wb + WOFF_2, wl + wb + WOFF_2, FF, 0, 0,
                   x, nullptr, nullptr, CC, 0, 0, MM, CC, FF, 1, 1, b2 + l * CC, 1, 2);
        }
    }
    ln_kernel<<<MM, 256>>>(x, xnh, xnl, lnfg, lnfb);
    run_hm(xnh, xnl, CC, 0, 0, wh + WOFF_HD, wl + WOFF_HD, CC, 0, 0,
           out, nullptr, nullptr, CC, 0, 0, MM, CC, CC, 1, 1, nullptr, 1, 0);
}